// round 10
// baseline (speedup 1.0000x reference)
#include <cuda_runtime.h>
#include <math.h>

// ---------------- problem constants ----------------
#define BB   128
#define NN   196
#define ENC  2048
#define DEC  512
#define ATT  512
#define EMB  512
#define VV   10000
#define TT   20          // T-1 steps
#define MM   (BB*NN)     // 25088
#define XK   3072        // EMB + ENC + DEC
#define G4   2048        // 4*DEC

// ---------------- scratch ----------------
__device__ float g_uhs[MM * ATT];            // 51.4 MB
__device__ float g_wcomb[XK * G4];           // 25.2 MB
__device__ float g_gbias[G4];
__device__ float g_mean[BB * ENC];
__device__ float g_h[BB * DEC];
__device__ float g_c[BB * DEC];
__device__ float g_wah[BB * ATT];
__device__ float g_scores[BB * NN];
__device__ float g_alpha[BB * NN];
__device__ float g_ctx[BB * ENC];
__device__ float g_x[BB * XK];
__device__ float g_gates[BB * G4];
__device__ float g_part[4 * BB * G4];        // split-K partials (max case)

// ---------------- mean over N ----------------
__global__ void __launch_bounds__(256) mean_kernel(const float* __restrict__ features,
                                                   float* __restrict__ meanf)
{
    int b = blockIdx.y;
    int e = blockIdx.x * 256 + threadIdx.x;            // 0..2047
    const float* f = features + (size_t)b * NN * ENC + e;
    float acc = 0.f;
#pragma unroll 4
    for (int n = 0; n < NN; n++) acc += f[(size_t)n * ENC];
    meanf[b * ENC + e] = acc * (1.0f / 196.0f);
}

// ---------------- build combined LSTM weight/bias ----------------
__global__ void buildcomb_kernel(const float* __restrict__ Wih, const float* __restrict__ Whh,
                                 const float* __restrict__ bih, const float* __restrict__ bhh,
                                 float* __restrict__ Wc, float* __restrict__ gb)
{
    int idx = blockIdx.x * 256 + threadIdx.x;
    if (idx < G4) gb[idx] = bih[idx] + bhh[idx];
    if (idx < XK * G4)
        Wc[idx] = (idx < (EMB + ENC) * G4) ? Wih[idx] : Whh[idx - (EMB + ENC) * G4];
}

// ---------------- big SGEMM: 128x128 tile, 8x8 per thread ----------------
// C[M,N] = A[M,K] @ B[K,N] + bias[N].  M%128==0, N%128==0, K%8==0.
__global__ void __launch_bounds__(256) gemm128_kernel(const float* __restrict__ A,
                                                      const float* __restrict__ B,
                                                      const float* __restrict__ bias,
                                                      float* __restrict__ C,
                                                      int M, int N, int K)
{
    __shared__ float As[8][132];
    __shared__ float Bs[8][128];
    int tid = threadIdx.x;
    int tx = tid & 15, ty = tid >> 4;
    int m0 = blockIdx.y * 128, n0 = blockIdx.x * 128;

    int arow = tid >> 1, acol = (tid & 1) * 4;
    int brow = tid >> 5, bcol = (tid & 31) * 4;

    const float* Aptr = A + (size_t)(m0 + arow) * K + acol;
    const float* Bptr = B + (size_t)brow * N + n0 + bcol;

    float acc[8][8];
#pragma unroll
    for (int i = 0; i < 8; i++)
#pragma unroll
        for (int j = 0; j < 8; j++) acc[i][j] = 0.f;

    for (int k0 = 0; k0 < K; k0 += 8) {
        float4 a4 = *(const float4*)(Aptr + k0);
        As[acol + 0][arow] = a4.x; As[acol + 1][arow] = a4.y;
        As[acol + 2][arow] = a4.z; As[acol + 3][arow] = a4.w;
        float4 b4 = *(const float4*)(Bptr + (size_t)k0 * N);
        *(float4*)&Bs[brow][bcol] = b4;
        __syncthreads();
#pragma unroll
        for (int kk = 0; kk < 8; kk++) {
            float ra[8], rb[8];
#pragma unroll
            for (int i = 0; i < 8; i++) ra[i] = As[kk][ty * 8 + i];
#pragma unroll
            for (int j = 0; j < 8; j++) rb[j] = Bs[kk][tx * 8 + j];
#pragma unroll
            for (int i = 0; i < 8; i++)
#pragma unroll
                for (int j = 0; j < 8; j++) acc[i][j] += ra[i] * rb[j];
        }
        __syncthreads();
    }
#pragma unroll
    for (int i = 0; i < 8; i++) {
        int m = m0 + ty * 8 + i;
#pragma unroll
        for (int j = 0; j < 8; j++) {
            int n = n0 + tx * 8 + j;
            C[(size_t)m * N + n] = acc[i][j] + bias[n];
        }
    }
}

// ---------------- small-M SGEMM: 64x64 tile, 4x4 per thread, optional split-K ----------------
// mode 0: C[m*ldc+n] = acc + bias[n]        (grid.z must be 1)
// mode 1: part[z*M*N + m*N + n] = acc       (split-K partials, deterministic reduce later)
__global__ void __launch_bounds__(256) gemm64_kernel(const float* __restrict__ A,
                                                     const float* __restrict__ B,
                                                     const float* __restrict__ bias,
                                                     float* __restrict__ C,
                                                     int M, int N, int K,
                                                     int ldc, int kSplit, int mode)
{
    __shared__ float As[16][68];
    __shared__ float Bs[16][64];
    int tid = threadIdx.x;
    int tx = tid & 15, ty = tid >> 4;
    int m0 = blockIdx.y * 64, n0 = blockIdx.x * 64;
    int kPer = K / kSplit;
    int kBase = blockIdx.z * kPer;

    int arow = tid >> 2, acol = (tid & 3) * 4;
    int brow = tid >> 4, bcol = (tid & 15) * 4;
    bool bok = (n0 + bcol) < N;

    const float* Aptr = A + (size_t)(m0 + arow) * K + kBase + acol;
    const float* Bptr = B + (size_t)(kBase + brow) * N + n0 + bcol;

    float acc[4][4];
#pragma unroll
    for (int i = 0; i < 4; i++)
#pragma unroll
        for (int j = 0; j < 4; j++) acc[i][j] = 0.f;

    for (int k0 = 0; k0 < kPer; k0 += 16) {
        float4 a4 = *(const float4*)(Aptr + k0);
        As[acol + 0][arow] = a4.x; As[acol + 1][arow] = a4.y;
        As[acol + 2][arow] = a4.z; As[acol + 3][arow] = a4.w;
        float4 b4 = bok ? *(const float4*)(Bptr + (size_t)k0 * N)
                        : make_float4(0.f, 0.f, 0.f, 0.f);
        *(float4*)&Bs[brow][bcol] = b4;
        __syncthreads();
#pragma unroll
        for (int kk = 0; kk < 16; kk++) {
            float ra[4], rb[4];
#pragma unroll
            for (int i = 0; i < 4; i++) ra[i] = As[kk][ty * 4 + i];
#pragma unroll
            for (int j = 0; j < 4; j++) rb[j] = Bs[kk][tx * 4 + j];
#pragma unroll
            for (int i = 0; i < 4; i++)
#pragma unroll
                for (int j = 0; j < 4; j++) acc[i][j] += ra[i] * rb[j];
        }
        __syncthreads();
    }
#pragma unroll
    for (int i = 0; i < 4; i++) {
        int m = m0 + ty * 4 + i;
#pragma unroll
        for (int j = 0; j < 4; j++) {
            int n = n0 + tx * 4 + j;
            if (n < N) {
                if (mode == 0)
                    C[(size_t)m * ldc + n] = acc[i][j] + (bias ? bias[n] : 0.f);
                else
                    C[(size_t)blockIdx.z * M * N + (size_t)m * N + n] = acc[i][j];
            }
        }
    }
}

// ---------------- split-K reduce: C = bias + sum_z part ----------------
__global__ void reduce_split_kernel(const float* __restrict__ part, const float* __restrict__ bias,
                                    float* __restrict__ C, int MN, int N, int S)
{
    int idx = blockIdx.x * 256 + threadIdx.x;
    if (idx >= MN) return;
    float acc = bias[idx % N];
    for (int z = 0; z < S; z++) acc += part[(size_t)z * MN + idx];
    C[idx] = acc;
}

// ---------------- scores: one warp per (b,n) ----------------
__global__ void __launch_bounds__(256) scores_kernel(const float* __restrict__ uhs,
                                                     const float* __restrict__ wah,
                                                     const float* __restrict__ Aw,
                                                     const float* __restrict__ Ab,
                                                     float* __restrict__ scores)
{
    int warp = (blockIdx.x * 256 + threadIdx.x) >> 5;
    int lane = threadIdx.x & 31;
    if (warp >= BB * NN) return;
    int b = warp / NN;
    const float* u = uhs + (size_t)warp * ATT;
    const float* w = wah + (size_t)b * ATT;
    float acc = 0.f;
#pragma unroll
    for (int a = lane; a < ATT; a += 32)
        acc += tanhf(u[a] + w[a]) * Aw[a];
#pragma unroll
    for (int off = 16; off > 0; off >>= 1)
        acc += __shfl_xor_sync(0xffffffffu, acc, off);
    if (lane == 0) scores[warp] = acc + Ab[0];
}

// ---------------- softmax over N per batch; also writes output alphas ----------------
__global__ void __launch_bounds__(256) softmax_kernel(const float* __restrict__ scores,
                                                      float* __restrict__ alpha,
                                                      float* __restrict__ outA, int t)
{
    int b = blockIdx.x, tid = threadIdx.x;
    __shared__ float red[256];
    float v = (tid < NN) ? scores[b * NN + tid] : -1e30f;
    float orig = v;
    red[tid] = v; __syncthreads();
    for (int off = 128; off > 0; off >>= 1) {
        if (tid < off) red[tid] = fmaxf(red[tid], red[tid + off]);
        __syncthreads();
    }
    float mx = red[0]; __syncthreads();
    float e = (tid < NN) ? expf(orig - mx) : 0.f;
    red[tid] = e; __syncthreads();
    for (int off = 128; off > 0; off >>= 1) {
        if (tid < off) red[tid] += red[tid + off];
        __syncthreads();
    }
    float inv = 1.f / red[0];
    if (tid < NN) {
        float a = e * inv;
        alpha[b * NN + tid] = a;
        outA[(size_t)b * (TT * NN) + t * NN + tid] = a;
    }
}

// ---------------- context = alpha @ features ----------------
__global__ void __launch_bounds__(256) context_kernel(const float* __restrict__ features,
                                                      const float* __restrict__ alpha,
                                                      float* __restrict__ ctx)
{
    int b = blockIdx.y;
    int e = blockIdx.x * 256 + threadIdx.x;
    __shared__ float sal[NN];
    if (threadIdx.x < NN) sal[threadIdx.x] = alpha[b * NN + threadIdx.x];
    __syncthreads();
    const float* f = features + (size_t)b * NN * ENC + e;
    float acc = 0.f;
#pragma unroll 4
    for (int n = 0; n < NN; n++) acc += sal[n] * f[(size_t)n * ENC];
    ctx[b * ENC + e] = acc;
}

// ---------------- build x = [emb_t | context | h] ----------------
__global__ void __launch_bounds__(256) xcat_kernel(const float* __restrict__ emb,
                                                   const int* __restrict__ captions,
                                                   const float* __restrict__ ctx,
                                                   const float* __restrict__ h,
                                                   float* __restrict__ x, int t)
{
    int b = blockIdx.y;
    int j = blockIdx.x * 256 + threadIdx.x;   // 0..3071
    float v;
    if (j < EMB) {
        int cap = captions[b * (TT + 1) + t];
        v = emb[(size_t)cap * EMB + j];
    } else if (j < EMB + ENC) {
        v = ctx[b * ENC + (j - EMB)];
    } else {
        v = h[b * DEC + (j - EMB - ENC)];
    }
    x[b * XK + j] = v;
}

// ---------------- LSTM pointwise ----------------
__global__ void __launch_bounds__(256) lstm_kernel(const float* __restrict__ gates,
                                                   float* __restrict__ h, float* __restrict__ c)
{
    int idx = blockIdx.x * 256 + threadIdx.x;
    if (idx >= BB * DEC) return;
    int b = idx >> 9, j = idx & (DEC - 1);
    const float* g = gates + b * G4;
    float ig = g[j], fg = g[DEC + j], gg = g[2 * DEC + j], og = g[3 * DEC + j];
    float si = 1.f / (1.f + expf(-ig));
    float sf = 1.f / (1.f + expf(-fg));
    float so = 1.f / (1.f + expf(-og));
    float cc = sf * c[idx] + si * tanhf(gg);
    float hh = so * tanhf(cc);
    c[idx] = cc;
    h[idx] = hh;
}

// ---------------- launch ----------------
extern "C" void kernel_launch(void* const* d_in, const int* in_sizes, int n_in,
                              void* d_out, int out_size)
{
    (void)in_sizes; (void)n_in; (void)out_size;
    const float* features = (const float*)d_in[0];
    const int*   captions = (const int*)d_in[1];
    const float* emb   = (const float*)d_in[2];
    const float* U_w   = (const float*)d_in[3];
    const float* U_b   = (const float*)d_in[4];
    const float* W_w   = (const float*)d_in[5];
    const float* W_b   = (const float*)d_in[6];
    const float* A_w   = (const float*)d_in[7];
    const float* A_b   = (const float*)d_in[8];
    const float* ih_w  = (const float*)d_in[9];
    const float* ih_b  = (const float*)d_in[10];
    const float* ic_w  = (const float*)d_in[11];
    const float* ic_b  = (const float*)d_in[12];
    const float* Wih   = (const float*)d_in[13];
    const float* Whh   = (const float*)d_in[14];
    const float* bih   = (const float*)d_in[15];
    const float* bhh   = (const float*)d_in[16];
    const float* fcn_w = (const float*)d_in[17];
    const float* fcn_b = (const float*)d_in[18];

    float* out    = (float*)d_out;
    float* preds  = out;                       // [B, 20, V]
    float* alphas = out + (size_t)BB * TT * VV; // [B, 20, N]

    float *uhs, *wcomb, *gbias, *meanf, *h, *c, *wah, *scores, *alpha, *ctx, *x, *gates, *part;
    cudaGetSymbolAddress((void**)&uhs,   g_uhs);
    cudaGetSymbolAddress((void**)&wcomb, g_wcomb);
    cudaGetSymbolAddress((void**)&gbias, g_gbias);
    cudaGetSymbolAddress((void**)&meanf, g_mean);
    cudaGetSymbolAddress((void**)&h,     g_h);
    cudaGetSymbolAddress((void**)&c,     g_c);
    cudaGetSymbolAddress((void**)&wah,   g_wah);
    cudaGetSymbolAddress((void**)&scores,g_scores);
    cudaGetSymbolAddress((void**)&alpha, g_alpha);
    cudaGetSymbolAddress((void**)&ctx,   g_ctx);
    cudaGetSymbolAddress((void**)&x,     g_x);
    cudaGetSymbolAddress((void**)&gates, g_gates);
    cudaGetSymbolAddress((void**)&part,  g_part);

    // ---- precompute ----
    mean_kernel<<<dim3(ENC / 256, BB), 256>>>(features, meanf);
    gemm64_kernel<<<dim3(DEC / 64, BB / 64, 1), 256>>>(meanf, ih_w, ih_b, h,
                                                       BB, DEC, ENC, DEC, 1, 0);
    gemm64_kernel<<<dim3(DEC / 64, BB / 64, 1), 256>>>(meanf, ic_w, ic_b, c,
                                                       BB, DEC, ENC, DEC, 1, 0);
    buildcomb_kernel<<<(XK * G4 + 255) / 256, 256>>>(Wih, Whh, bih, bhh, wcomb, gbias);
    gemm128_kernel<<<dim3(ATT / 128, MM / 128), 256>>>(features, U_w, U_b, uhs,
                                                       MM, ATT, ENC);

    // ---- sequential decode ----
    for (int t = 0; t < TT; t++) {
        // w_ah = h @ W_w + W_b   (split-K x4)
        gemm64_kernel<<<dim3(ATT / 64, BB / 64, 4), 256>>>(h, W_w, nullptr, part,
                                                           BB, ATT, DEC, ATT, 4, 1);
        reduce_split_kernel<<<(BB * ATT + 255) / 256, 256>>>(part, W_b, wah,
                                                             BB * ATT, ATT, 4);
        // scores = tanh(u_hs + w_ah) . A_w + A_b
        scores_kernel<<<(BB * NN * 32) / 256, 256>>>(uhs, wah, A_w, A_b, scores);
        // alpha = softmax(scores); also write output alphas
        softmax_kernel<<<BB, 256>>>(scores, alpha, alphas, t);
        // context = alpha @ features
        context_kernel<<<dim3(ENC / 256, BB), 256>>>(features, alpha, ctx);
        // x = [emb_t | context | h]
        xcat_kernel<<<dim3(XK / 256, BB), 256>>>(emb, captions, ctx, h, x, t);
        // gates = x @ Wcomb + (bih+bhh)  (split-K x4)
        gemm64_kernel<<<dim3(G4 / 64, BB / 64, 4), 256>>>(x, wcomb, nullptr, part,
                                                          BB, G4, XK, G4, 4, 1);
        reduce_split_kernel<<<(BB * G4 + 255) / 256, 256>>>(part, gbias, gates,
                                                            BB * G4, G4, 4);
        // LSTM pointwise update
        lstm_kernel<<<(BB * DEC + 255) / 256, 256>>>(gates, h, c);
        // preds[:, t, :] = h @ fcn_w + fcn_b
        gemm64_kernel<<<dim3((VV + 63) / 64, BB / 64, 1), 256>>>(h, fcn_w, fcn_b,
                                                                 preds + (size_t)t * VV,
                                                                 BB, VV, DEC, TT * VV, 1, 0);
    }
}

// round 11
// speedup vs baseline: 1.0002x; 1.0002x over previous
#include <cuda_runtime.h>
#include <math.h>

// ---------------- problem constants ----------------
#define BB   128
#define NN   196
#define ENC  2048
#define DEC  512
#define ATT  512
#define EMB  512
#define VV   10000
#define TT   20          // T-1 steps
#define MM   (BB*NN)     // 25088
#define XK   3072        // EMB + ENC + DEC
#define G4   2048        // 4*DEC

// ---------------- scratch ----------------
__device__ float g_uhs[MM * ATT];            // 51.4 MB
__device__ float g_wcomb[XK * G4];           // 25.2 MB
__device__ float g_gbias[G4];
__device__ float g_mean[BB * ENC];
__device__ float g_h[BB * DEC];
__device__ float g_c[BB * DEC];
__device__ float g_wah[BB * ATT];
__device__ float g_scores[BB * NN];
__device__ float g_alpha[BB * NN];
__device__ float g_ctx[BB * ENC];
__device__ float g_x[BB * XK];
__device__ float g_gates[BB * G4];
__device__ float g_part[4 * BB * G4];        // split-K partials (max case)

// ---------------- mean over N ----------------
__global__ void __launch_bounds__(256) mean_kernel(const float* __restrict__ features,
                                                   float* __restrict__ meanf)
{
    int b = blockIdx.y;
    int e = blockIdx.x * 256 + threadIdx.x;            // 0..2047
    const float* f = features + (size_t)b * NN * ENC + e;
    float acc = 0.f;
#pragma unroll 4
    for (int n = 0; n < NN; n++) acc += f[(size_t)n * ENC];
    meanf[b * ENC + e] = acc * (1.0f / 196.0f);
}

// ---------------- build combined LSTM weight/bias ----------------
__global__ void buildcomb_kernel(const float* __restrict__ Wih, const float* __restrict__ Whh,
                                 const float* __restrict__ bih, const float* __restrict__ bhh,
                                 float* __restrict__ Wc, float* __restrict__ gb)
{
    int idx = blockIdx.x * 256 + threadIdx.x;
    if (idx < G4) gb[idx] = bih[idx] + bhh[idx];
    if (idx < XK * G4)
        Wc[idx] = (idx < (EMB + ENC) * G4) ? Wih[idx] : Whh[idx - (EMB + ENC) * G4];
}

// ---------------- big SGEMM: 128x128 tile, 8x8 per thread ----------------
// C[M,N] = A[M,K] @ B[K,N] + bias[N].  M%128==0, N%128==0, K%8==0.
__global__ void __launch_bounds__(256) gemm128_kernel(const float* __restrict__ A,
                                                      const float* __restrict__ B,
                                                      const float* __restrict__ bias,
                                                      float* __restrict__ C,
                                                      int M, int N, int K)
{
    __shared__ float As[8][132];
    __shared__ float Bs[8][128];
    int tid = threadIdx.x;
    int tx = tid & 15, ty = tid >> 4;
    int m0 = blockIdx.y * 128, n0 = blockIdx.x * 128;

    int arow = tid >> 1, acol = (tid & 1) * 4;
    int brow = tid >> 5, bcol = (tid & 31) * 4;

    const float* Aptr = A + (size_t)(m0 + arow) * K + acol;
    const float* Bptr = B + (size_t)brow * N + n0 + bcol;

    float acc[8][8];
#pragma unroll
    for (int i = 0; i < 8; i++)
#pragma unroll
        for (int j = 0; j < 8; j++) acc[i][j] = 0.f;

    for (int k0 = 0; k0 < K; k0 += 8) {
        float4 a4 = *(const float4*)(Aptr + k0);
        As[acol + 0][arow] = a4.x; As[acol + 1][arow] = a4.y;
        As[acol + 2][arow] = a4.z; As[acol + 3][arow] = a4.w;
        float4 b4 = *(const float4*)(Bptr + (size_t)k0 * N);
        *(float4*)&Bs[brow][bcol] = b4;
        __syncthreads();
#pragma unroll
        for (int kk = 0; kk < 8; kk++) {
            float ra[8], rb[8];
#pragma unroll
            for (int i = 0; i < 8; i++) ra[i] = As[kk][ty * 8 + i];
#pragma unroll
            for (int j = 0; j < 8; j++) rb[j] = Bs[kk][tx * 8 + j];
#pragma unroll
            for (int i = 0; i < 8; i++)
#pragma unroll
                for (int j = 0; j < 8; j++) acc[i][j] += ra[i] * rb[j];
        }
        __syncthreads();
    }
#pragma unroll
    for (int i = 0; i < 8; i++) {
        int m = m0 + ty * 8 + i;
#pragma unroll
        for (int j = 0; j < 8; j++) {
            int n = n0 + tx * 8 + j;
            C[(size_t)m * N + n] = acc[i][j] + bias[n];
        }
    }
}

// ---------------- small-M SGEMM: 64x64 tile, 4x4 per thread, optional split-K ----------------
// mode 0: C[m*ldc+n] = acc + bias[n]        (grid.z must be 1)
// mode 1: part[z*M*N + m*N + n] = acc       (split-K partials, deterministic reduce later)
__global__ void __launch_bounds__(256) gemm64_kernel(const float* __restrict__ A,
                                                     const float* __restrict__ B,
                                                     const float* __restrict__ bias,
                                                     float* __restrict__ C,
                                                     int M, int N, int K,
                                                     int ldc, int kSplit, int mode)
{
    __shared__ float As[16][68];
    __shared__ float Bs[16][64];
    int tid = threadIdx.x;
    int tx = tid & 15, ty = tid >> 4;
    int m0 = blockIdx.y * 64, n0 = blockIdx.x * 64;
    int kPer = K / kSplit;
    int kBase = blockIdx.z * kPer;

    int arow = tid >> 2, acol = (tid & 3) * 4;
    int brow = tid >> 4, bcol = (tid & 15) * 4;
    bool bok = (n0 + bcol) < N;

    const float* Aptr = A + (size_t)(m0 + arow) * K + kBase + acol;
    const float* Bptr = B + (size_t)(kBase + brow) * N + n0 + bcol;

    float acc[4][4];
#pragma unroll
    for (int i = 0; i < 4; i++)
#pragma unroll
        for (int j = 0; j < 4; j++) acc[i][j] = 0.f;

    for (int k0 = 0; k0 < kPer; k0 += 16) {
        float4 a4 = *(const float4*)(Aptr + k0);
        As[acol + 0][arow] = a4.x; As[acol + 1][arow] = a4.y;
        As[acol + 2][arow] = a4.z; As[acol + 3][arow] = a4.w;
        float4 b4 = bok ? *(const float4*)(Bptr + (size_t)k0 * N)
                        : make_float4(0.f, 0.f, 0.f, 0.f);
        *(float4*)&Bs[brow][bcol] = b4;
        __syncthreads();
#pragma unroll
        for (int kk = 0; kk < 16; kk++) {
            float ra[4], rb[4];
#pragma unroll
            for (int i = 0; i < 4; i++) ra[i] = As[kk][ty * 4 + i];
#pragma unroll
            for (int j = 0; j < 4; j++) rb[j] = Bs[kk][tx * 4 + j];
#pragma unroll
            for (int i = 0; i < 4; i++)
#pragma unroll
                for (int j = 0; j < 4; j++) acc[i][j] += ra[i] * rb[j];
        }
        __syncthreads();
    }
#pragma unroll
    for (int i = 0; i < 4; i++) {
        int m = m0 + ty * 4 + i;
#pragma unroll
        for (int j = 0; j < 4; j++) {
            int n = n0 + tx * 4 + j;
            if (n < N) {
                if (mode == 0)
                    C[(size_t)m * ldc + n] = acc[i][j] + (bias ? bias[n] : 0.f);
                else
                    C[(size_t)blockIdx.z * M * N + (size_t)m * N + n] = acc[i][j];
            }
        }
    }
}

// ---------------- split-K reduce: C = bias + sum_z part ----------------
__global__ void reduce_split_kernel(const float* __restrict__ part, const float* __restrict__ bias,
                                    float* __restrict__ C, int MN, int N, int S)
{
    int idx = blockIdx.x * 256 + threadIdx.x;
    if (idx >= MN) return;
    float acc = bias[idx % N];
    for (int z = 0; z < S; z++) acc += part[(size_t)z * MN + idx];
    C[idx] = acc;
}

// ---------------- scores: one warp per (b,n) ----------------
__global__ void __launch_bounds__(256) scores_kernel(const float* __restrict__ uhs,
                                                     const float* __restrict__ wah,
                                                     const float* __restrict__ Aw,
                                                     const float* __restrict__ Ab,
                                                     float* __restrict__ scores)
{
    int warp = (blockIdx.x * 256 + threadIdx.x) >> 5;
    int lane = threadIdx.x & 31;
    if (warp >= BB * NN) return;
    int b = warp / NN;
    const float* u = uhs + (size_t)warp * ATT;
    const float* w = wah + (size_t)b * ATT;
    float acc = 0.f;
#pragma unroll
    for (int a = lane; a < ATT; a += 32)
        acc += tanhf(u[a] + w[a]) * Aw[a];
#pragma unroll
    for (int off = 16; off > 0; off >>= 1)
        acc += __shfl_xor_sync(0xffffffffu, acc, off);
    if (lane == 0) scores[warp] = acc + Ab[0];
}

// ---------------- softmax over N per batch; also writes output alphas ----------------
__global__ void __launch_bounds__(256) softmax_kernel(const float* __restrict__ scores,
                                                      float* __restrict__ alpha,
                                                      float* __restrict__ outA, int t)
{
    int b = blockIdx.x, tid = threadIdx.x;
    __shared__ float red[256];
    float v = (tid < NN) ? scores[b * NN + tid] : -1e30f;
    float orig = v;
    red[tid] = v; __syncthreads();
    for (int off = 128; off > 0; off >>= 1) {
        if (tid < off) red[tid] = fmaxf(red[tid], red[tid + off]);
        __syncthreads();
    }
    float mx = red[0]; __syncthreads();
    float e = (tid < NN) ? expf(orig - mx) : 0.f;
    red[tid] = e; __syncthreads();
    for (int off = 128; off > 0; off >>= 1) {
        if (tid < off) red[tid] += red[tid + off];
        __syncthreads();
    }
    float inv = 1.f / red[0];
    if (tid < NN) {
        float a = e * inv;
        alpha[b * NN + tid] = a;
        outA[(size_t)b * (TT * NN) + t * NN + tid] = a;
    }
}

// ---------------- context = alpha @ features ----------------
__global__ void __launch_bounds__(256) context_kernel(const float* __restrict__ features,
                                                      const float* __restrict__ alpha,
                                                      float* __restrict__ ctx)
{
    int b = blockIdx.y;
    int e = blockIdx.x * 256 + threadIdx.x;
    __shared__ float sal[NN];
    if (threadIdx.x < NN) sal[threadIdx.x] = alpha[b * NN + threadIdx.x];
    __syncthreads();
    const float* f = features + (size_t)b * NN * ENC + e;
    float acc = 0.f;
#pragma unroll 4
    for (int n = 0; n < NN; n++) acc += sal[n] * f[(size_t)n * ENC];
    ctx[b * ENC + e] = acc;
}

// ---------------- build x = [emb_t | context | h] ----------------
__global__ void __launch_bounds__(256) xcat_kernel(const float* __restrict__ emb,
                                                   const int* __restrict__ captions,
                                                   const float* __restrict__ ctx,
                                                   const float* __restrict__ h,
                                                   float* __restrict__ x, int t)
{
    int b = blockIdx.y;
    int j = blockIdx.x * 256 + threadIdx.x;   // 0..3071
    float v;
    if (j < EMB) {
        int cap = captions[b * (TT + 1) + t];
        v = emb[(size_t)cap * EMB + j];
    } else if (j < EMB + ENC) {
        v = ctx[b * ENC + (j - EMB)];
    } else {
        v = h[b * DEC + (j - EMB - ENC)];
    }
    x[b * XK + j] = v;
}

// ---------------- LSTM pointwise ----------------
__global__ void __launch_bounds__(256) lstm_kernel(const float* __restrict__ gates,
                                                   float* __restrict__ h, float* __restrict__ c)
{
    int idx = blockIdx.x * 256 + threadIdx.x;
    if (idx >= BB * DEC) return;
    int b = idx >> 9, j = idx & (DEC - 1);
    const float* g = gates + b * G4;
    float ig = g[j], fg = g[DEC + j], gg = g[2 * DEC + j], og = g[3 * DEC + j];
    float si = 1.f / (1.f + expf(-ig));
    float sf = 1.f / (1.f + expf(-fg));
    float so = 1.f / (1.f + expf(-og));
    float cc = sf * c[idx] + si * tanhf(gg);
    float hh = so * tanhf(cc);
    c[idx] = cc;
    h[idx] = hh;
}

// ---------------- launch ----------------
extern "C" void kernel_launch(void* const* d_in, const int* in_sizes, int n_in,
                              void* d_out, int out_size)
{
    (void)in_sizes; (void)n_in; (void)out_size;
    const float* features = (const float*)d_in[0];
    const int*   captions = (const int*)d_in[1];
    const float* emb   = (const float*)d_in[2];
    const float* U_w   = (const float*)d_in[3];
    const float* U_b   = (const float*)d_in[4];
    const float* W_w   = (const float*)d_in[5];
    const float* W_b   = (const float*)d_in[6];
    const float* A_w   = (const float*)d_in[7];
    const float* A_b   = (const float*)d_in[8];
    const float* ih_w  = (const float*)d_in[9];
    const float* ih_b  = (const float*)d_in[10];
    const float* ic_w  = (const float*)d_in[11];
    const float* ic_b  = (const float*)d_in[12];
    const float* Wih   = (const float*)d_in[13];
    const float* Whh   = (const float*)d_in[14];
    const float* bih   = (const float*)d_in[15];
    const float* bhh   = (const float*)d_in[16];
    const float* fcn_w = (const float*)d_in[17];
    const float* fcn_b = (const float*)d_in[18];

    float* out    = (float*)d_out;
    float* preds  = out;                       // [B, 20, V]
    float* alphas = out + (size_t)BB * TT * VV; // [B, 20, N]

    float *uhs, *wcomb, *gbias, *meanf, *h, *c, *wah, *scores, *alpha, *ctx, *x, *gates, *part;
    cudaGetSymbolAddress((void**)&uhs,   g_uhs);
    cudaGetSymbolAddress((void**)&wcomb, g_wcomb);
    cudaGetSymbolAddress((void**)&gbias, g_gbias);
    cudaGetSymbolAddress((void**)&meanf, g_mean);
    cudaGetSymbolAddress((void**)&h,     g_h);
    cudaGetSymbolAddress((void**)&c,     g_c);
    cudaGetSymbolAddress((void**)&wah,   g_wah);
    cudaGetSymbolAddress((void**)&scores,g_scores);
    cudaGetSymbolAddress((void**)&alpha, g_alpha);
    cudaGetSymbolAddress((void**)&ctx,   g_ctx);
    cudaGetSymbolAddress((void**)&x,     g_x);
    cudaGetSymbolAddress((void**)&gates, g_gates);
    cudaGetSymbolAddress((void**)&part,  g_part);

    // ---- precompute ----
    mean_kernel<<<dim3(ENC / 256, BB), 256>>>(features, meanf);
    gemm64_kernel<<<dim3(DEC / 64, BB / 64, 1), 256>>>(meanf, ih_w, ih_b, h,
                                                       BB, DEC, ENC, DEC, 1, 0);
    gemm64_kernel<<<dim3(DEC / 64, BB / 64, 1), 256>>>(meanf, ic_w, ic_b, c,
                                                       BB, DEC, ENC, DEC, 1, 0);
    buildcomb_kernel<<<(XK * G4 + 255) / 256, 256>>>(Wih, Whh, bih, bhh, wcomb, gbias);
    gemm128_kernel<<<dim3(ATT / 128, MM / 128), 256>>>(features, U_w, U_b, uhs,
                                                       MM, ATT, ENC);

    // ---- sequential decode ----
    for (int t = 0; t < TT; t++) {
        // w_ah = h @ W_w + W_b   (split-K x4)
        gemm64_kernel<<<dim3(ATT / 64, BB / 64, 4), 256>>>(h, W_w, nullptr, part,
                                                           BB, ATT, DEC, ATT, 4, 1);
        reduce_split_kernel<<<(BB * ATT + 255) / 256, 256>>>(part, W_b, wah,
                                                             BB * ATT, ATT, 4);
        // scores = tanh(u_hs + w_ah) . A_w + A_b
        scores_kernel<<<(BB * NN * 32) / 256, 256>>>(uhs, wah, A_w, A_b, scores);
        // alpha = softmax(scores); also write output alphas
        softmax_kernel<<<BB, 256>>>(scores, alpha, alphas, t);
        // context = alpha @ features
        context_kernel<<<dim3(ENC / 256, BB), 256>>>(features, alpha, ctx);
        // x = [emb_t | context | h]
        xcat_kernel<<<dim3(XK / 256, BB), 256>>>(emb, captions, ctx, h, x, t);
        // gates = x @ Wcomb + (bih+bhh)  (split-K x4)
        gemm64_kernel<<<dim3(G4 / 64, BB / 64, 4), 256>>>(x, wcomb, nullptr, part,
                                                          BB, G4, XK, G4, 4, 1);
        reduce_split_kernel<<<(BB * G4 + 255) / 256, 256>>>(part, gbias, gates,
                                                            BB * G4, G4, 4);
        // LSTM pointwise update
        lstm_kernel<<<(BB * DEC + 255) / 256, 256>>>(gates, h, c);
        // preds[:, t, :] = h @ fcn_w + fcn_b
        gemm64_kernel<<<dim3((VV + 63) / 64, BB / 64, 1), 256>>>(h, fcn_w, fcn_b,
                                                                 preds + (size_t)t * VV,
                                                                 BB, VV, DEC, TT * VV, 1, 0);
    }
}

// round 12
// speedup vs baseline: 1.0006x; 1.0004x over previous
#include <cuda_runtime.h>
#include <math.h>

// ---------------- problem constants ----------------
#define BB   128
#define NN   196
#define ENC  2048
#define DEC  512
#define ATT  512
#define EMB  512
#define VV   10000
#define TT   20          // T-1 steps
#define MM   (BB*NN)     // 25088
#define XK   3072        // EMB + ENC + DEC
#define G4   2048        // 4*DEC

// ---------------- scratch ----------------
__device__ float g_uhs[MM * ATT];            // 51.4 MB
__device__ float g_wcomb[XK * G4];           // 25.2 MB
__device__ float g_gbias[G4];
__device__ float g_mean[BB * ENC];
__device__ float g_h[BB * DEC];
__device__ float g_c[BB * DEC];
__device__ float g_wah[BB * ATT];
__device__ float g_scores[BB * NN];
__device__ float g_alpha[BB * NN];
__device__ float g_ctx[BB * ENC];
__device__ float g_x[BB * XK];
__device__ float g_gates[BB * G4];
__device__ float g_part[4 * BB * G4];        // split-K partials (max case)

// ---------------- mean over N ----------------
__global__ void __launch_bounds__(256) mean_kernel(const float* __restrict__ features,
                                                   float* __restrict__ meanf)
{
    int b = blockIdx.y;
    int e = blockIdx.x * 256 + threadIdx.x;            // 0..2047
    const float* f = features + (size_t)b * NN * ENC + e;
    float acc = 0.f;
#pragma unroll 4
    for (int n = 0; n < NN; n++) acc += f[(size_t)n * ENC];
    meanf[b * ENC + e] = acc * (1.0f / 196.0f);
}

// ---------------- build combined LSTM weight/bias ----------------
__global__ void buildcomb_kernel(const float* __restrict__ Wih, const float* __restrict__ Whh,
                                 const float* __restrict__ bih, const float* __restrict__ bhh,
                                 float* __restrict__ Wc, float* __restrict__ gb)
{
    int idx = blockIdx.x * 256 + threadIdx.x;
    if (idx < G4) gb[idx] = bih[idx] + bhh[idx];
    if (idx < XK * G4)
        Wc[idx] = (idx < (EMB + ENC) * G4) ? Wih[idx] : Whh[idx - (EMB + ENC) * G4];
}

// ---------------- big SGEMM: 128x128 tile, 8x8 per thread ----------------
// C[M,N] = A[M,K] @ B[K,N] + bias[N].  M%128==0, N%128==0, K%8==0.
__global__ void __launch_bounds__(256) gemm128_kernel(const float* __restrict__ A,
                                                      const float* __restrict__ B,
                                                      const float* __restrict__ bias,
                                                      float* __restrict__ C,
                                                      int M, int N, int K)
{
    __shared__ float As[8][132];
    __shared__ float Bs[8][128];
    int tid = threadIdx.x;
    int tx = tid & 15, ty = tid >> 4;
    int m0 = blockIdx.y * 128, n0 = blockIdx.x * 128;

    int arow = tid >> 1, acol = (tid & 1) * 4;
    int brow = tid >> 5, bcol = (tid & 31) * 4;

    const float* Aptr = A + (size_t)(m0 + arow) * K + acol;
    const float* Bptr = B + (size_t)brow * N + n0 + bcol;

    float acc[8][8];
#pragma unroll
    for (int i = 0; i < 8; i++)
#pragma unroll
        for (int j = 0; j < 8; j++) acc[i][j] = 0.f;

    for (int k0 = 0; k0 < K; k0 += 8) {
        float4 a4 = *(const float4*)(Aptr + k0);
        As[acol + 0][arow] = a4.x; As[acol + 1][arow] = a4.y;
        As[acol + 2][arow] = a4.z; As[acol + 3][arow] = a4.w;
        float4 b4 = *(const float4*)(Bptr + (size_t)k0 * N);
        *(float4*)&Bs[brow][bcol] = b4;
        __syncthreads();
#pragma unroll
        for (int kk = 0; kk < 8; kk++) {
            float ra[8], rb[8];
#pragma unroll
            for (int i = 0; i < 8; i++) ra[i] = As[kk][ty * 8 + i];
#pragma unroll
            for (int j = 0; j < 8; j++) rb[j] = Bs[kk][tx * 8 + j];
#pragma unroll
            for (int i = 0; i < 8; i++)
#pragma unroll
                for (int j = 0; j < 8; j++) acc[i][j] += ra[i] * rb[j];
        }
        __syncthreads();
    }
#pragma unroll
    for (int i = 0; i < 8; i++) {
        int m = m0 + ty * 8 + i;
#pragma unroll
        for (int j = 0; j < 8; j++) {
            int n = n0 + tx * 8 + j;
            C[(size_t)m * N + n] = acc[i][j] + bias[n];
        }
    }
}

// ---------------- small-M SGEMM: 64x64 tile, 4x4 per thread, optional split-K ----------------
// mode 0: C[m*ldc+n] = acc + bias[n]        (grid.z must be 1)
// mode 1: part[z*M*N + m*N + n] = acc       (split-K partials, deterministic reduce later)
__global__ void __launch_bounds__(256) gemm64_kernel(const float* __restrict__ A,
                                                     const float* __restrict__ B,
                                                     const float* __restrict__ bias,
                                                     float* __restrict__ C,
                                                     int M, int N, int K,
                                                     int ldc, int kSplit, int mode)
{
    __shared__ float As[16][68];
    __shared__ float Bs[16][64];
    int tid = threadIdx.x;
    int tx = tid & 15, ty = tid >> 4;
    int m0 = blockIdx.y * 64, n0 = blockIdx.x * 64;
    int kPer = K / kSplit;
    int kBase = blockIdx.z * kPer;

    int arow = tid >> 2, acol = (tid & 3) * 4;
    int brow = tid >> 4, bcol = (tid & 15) * 4;
    bool bok = (n0 + bcol) < N;

    const float* Aptr = A + (size_t)(m0 + arow) * K + kBase + acol;
    const float* Bptr = B + (size_t)(kBase + brow) * N + n0 + bcol;

    float acc[4][4];
#pragma unroll
    for (int i = 0; i < 4; i++)
#pragma unroll
        for (int j = 0; j < 4; j++) acc[i][j] = 0.f;

    for (int k0 = 0; k0 < kPer; k0 += 16) {
        float4 a4 = *(const float4*)(Aptr + k0);
        As[acol + 0][arow] = a4.x; As[acol + 1][arow] = a4.y;
        As[acol + 2][arow] = a4.z; As[acol + 3][arow] = a4.w;
        float4 b4 = bok ? *(const float4*)(Bptr + (size_t)k0 * N)
                        : make_float4(0.f, 0.f, 0.f, 0.f);
        *(float4*)&Bs[brow][bcol] = b4;
        __syncthreads();
#pragma unroll
        for (int kk = 0; kk < 16; kk++) {
            float ra[4], rb[4];
#pragma unroll
            for (int i = 0; i < 4; i++) ra[i] = As[kk][ty * 4 + i];
#pragma unroll
            for (int j = 0; j < 4; j++) rb[j] = Bs[kk][tx * 4 + j];
#pragma unroll
            for (int i = 0; i < 4; i++)
#pragma unroll
                for (int j = 0; j < 4; j++) acc[i][j] += ra[i] * rb[j];
        }
        __syncthreads();
    }
#pragma unroll
    for (int i = 0; i < 4; i++) {
        int m = m0 + ty * 4 + i;
#pragma unroll
        for (int j = 0; j < 4; j++) {
            int n = n0 + tx * 4 + j;
            if (n < N) {
                if (mode == 0)
                    C[(size_t)m * ldc + n] = acc[i][j] + (bias ? bias[n] : 0.f);
                else
                    C[(size_t)blockIdx.z * M * N + (size_t)m * N + n] = acc[i][j];
            }
        }
    }
}

// ---------------- split-K reduce: C = bias + sum_z part ----------------
__global__ void reduce_split_kernel(const float* __restrict__ part, const float* __restrict__ bias,
                                    float* __restrict__ C, int MN, int N, int S)
{
    int idx = blockIdx.x * 256 + threadIdx.x;
    if (idx >= MN) return;
    float acc = bias[idx % N];
    for (int z = 0; z < S; z++) acc += part[(size_t)z * MN + idx];
    C[idx] = acc;
}

// ---------------- scores: one warp per (b,n) ----------------
__global__ void __launch_bounds__(256) scores_kernel(const float* __restrict__ uhs,
                                                     const float* __restrict__ wah,
                                                     const float* __restrict__ Aw,
                                                     const float* __restrict__ Ab,
                                                     float* __restrict__ scores)
{
    int warp = (blockIdx.x * 256 + threadIdx.x) >> 5;
    int lane = threadIdx.x & 31;
    if (warp >= BB * NN) return;
    int b = warp / NN;
    const float* u = uhs + (size_t)warp * ATT;
    const float* w = wah + (size_t)b * ATT;
    float acc = 0.f;
#pragma unroll
    for (int a = lane; a < ATT; a += 32)
        acc += tanhf(u[a] + w[a]) * Aw[a];
#pragma unroll
    for (int off = 16; off > 0; off >>= 1)
        acc += __shfl_xor_sync(0xffffffffu, acc, off);
    if (lane == 0) scores[warp] = acc + Ab[0];
}

// ---------------- softmax over N per batch; also writes output alphas ----------------
__global__ void __launch_bounds__(256) softmax_kernel(const float* __restrict__ scores,
                                                      float* __restrict__ alpha,
                                                      float* __restrict__ outA, int t)
{
    int b = blockIdx.x, tid = threadIdx.x;
    __shared__ float red[256];
    float v = (tid < NN) ? scores[b * NN + tid] : -1e30f;
    float orig = v;
    red[tid] = v; __syncthreads();
    for (int off = 128; off > 0; off >>= 1) {
        if (tid < off) red[tid] = fmaxf(red[tid], red[tid + off]);
        __syncthreads();
    }
    float mx = red[0]; __syncthreads();
    float e = (tid < NN) ? expf(orig - mx) : 0.f;
    red[tid] = e; __syncthreads();
    for (int off = 128; off > 0; off >>= 1) {
        if (tid < off) red[tid] += red[tid + off];
        __syncthreads();
    }
    float inv = 1.f / red[0];
    if (tid < NN) {
        float a = e * inv;
        alpha[b * NN + tid] = a;
        outA[(size_t)b * (TT * NN) + t * NN + tid] = a;
    }
}

// ---------------- context = alpha @ features ----------------
__global__ void __launch_bounds__(256) context_kernel(const float* __restrict__ features,
                                                      const float* __restrict__ alpha,
                                                      float* __restrict__ ctx)
{
    int b = blockIdx.y;
    int e = blockIdx.x * 256 + threadIdx.x;
    __shared__ float sal[NN];
    if (threadIdx.x < NN) sal[threadIdx.x] = alpha[b * NN + threadIdx.x];
    __syncthreads();
    const float* f = features + (size_t)b * NN * ENC + e;
    float acc = 0.f;
#pragma unroll 4
    for (int n = 0; n < NN; n++) acc += sal[n] * f[(size_t)n * ENC];
    ctx[b * ENC + e] = acc;
}

// ---------------- build x = [emb_t | context | h] ----------------
__global__ void __launch_bounds__(256) xcat_kernel(const float* __restrict__ emb,
                                                   const int* __restrict__ captions,
                                                   const float* __restrict__ ctx,
                                                   const float* __restrict__ h,
                                                   float* __restrict__ x, int t)
{
    int b = blockIdx.y;
    int j = blockIdx.x * 256 + threadIdx.x;   // 0..3071
    float v;
    if (j < EMB) {
        int cap = captions[b * (TT + 1) + t];
        v = emb[(size_t)cap * EMB + j];
    } else if (j < EMB + ENC) {
        v = ctx[b * ENC + (j - EMB)];
    } else {
        v = h[b * DEC + (j - EMB - ENC)];
    }
    x[b * XK + j] = v;
}

// ---------------- LSTM pointwise ----------------
__global__ void __launch_bounds__(256) lstm_kernel(const float* __restrict__ gates,
                                                   float* __restrict__ h, float* __restrict__ c)
{
    int idx = blockIdx.x * 256 + threadIdx.x;
    if (idx >= BB * DEC) return;
    int b = idx >> 9, j = idx & (DEC - 1);
    const float* g = gates + b * G4;
    float ig = g[j], fg = g[DEC + j], gg = g[2 * DEC + j], og = g[3 * DEC + j];
    float si = 1.f / (1.f + expf(-ig));
    float sf = 1.f / (1.f + expf(-fg));
    float so = 1.f / (1.f + expf(-og));
    float cc = sf * c[idx] + si * tanhf(gg);
    float hh = so * tanhf(cc);
    c[idx] = cc;
    h[idx] = hh;
}

// ---------------- launch ----------------
extern "C" void kernel_launch(void* const* d_in, const int* in_sizes, int n_in,
                              void* d_out, int out_size)
{
    (void)in_sizes; (void)n_in; (void)out_size;
    const float* features = (const float*)d_in[0];
    const int*   captions = (const int*)d_in[1];
    const float* emb   = (const float*)d_in[2];
    const float* U_w   = (const float*)d_in[3];
    const float* U_b   = (const float*)d_in[4];
    const float* W_w   = (const float*)d_in[5];
    const float* W_b   = (const float*)d_in[6];
    const float* A_w   = (const float*)d_in[7];
    const float* A_b   = (const float*)d_in[8];
    const float* ih_w  = (const float*)d_in[9];
    const float* ih_b  = (const float*)d_in[10];
    const float* ic_w  = (const float*)d_in[11];
    const float* ic_b  = (const float*)d_in[12];
    const float* Wih   = (const float*)d_in[13];
    const float* Whh   = (const float*)d_in[14];
    const float* bih   = (const float*)d_in[15];
    const float* bhh   = (const float*)d_in[16];
    const float* fcn_w = (const float*)d_in[17];
    const float* fcn_b = (const float*)d_in[18];

    float* out    = (float*)d_out;
    float* preds  = out;                       // [B, 20, V]
    float* alphas = out + (size_t)BB * TT * VV; // [B, 20, N]

    float *uhs, *wcomb, *gbias, *meanf, *h, *c, *wah, *scores, *alpha, *ctx, *x, *gates, *part;
    cudaGetSymbolAddress((void**)&uhs,   g_uhs);
    cudaGetSymbolAddress((void**)&wcomb, g_wcomb);
    cudaGetSymbolAddress((void**)&gbias, g_gbias);
    cudaGetSymbolAddress((void**)&meanf, g_mean);
    cudaGetSymbolAddress((void**)&h,     g_h);
    cudaGetSymbolAddress((void**)&c,     g_c);
    cudaGetSymbolAddress((void**)&wah,   g_wah);
    cudaGetSymbolAddress((void**)&scores,g_scores);
    cudaGetSymbolAddress((void**)&alpha, g_alpha);
    cudaGetSymbolAddress((void**)&ctx,   g_ctx);
    cudaGetSymbolAddress((void**)&x,     g_x);
    cudaGetSymbolAddress((void**)&gates, g_gates);
    cudaGetSymbolAddress((void**)&part,  g_part);

    // ---- precompute ----
    mean_kernel<<<dim3(ENC / 256, BB), 256>>>(features, meanf);
    gemm64_kernel<<<dim3(DEC / 64, BB / 64, 1), 256>>>(meanf, ih_w, ih_b, h,
                                                       BB, DEC, ENC, DEC, 1, 0);
    gemm64_kernel<<<dim3(DEC / 64, BB / 64, 1), 256>>>(meanf, ic_w, ic_b, c,
                                                       BB, DEC, ENC, DEC, 1, 0);
    buildcomb_kernel<<<(XK * G4 + 255) / 256, 256>>>(Wih, Whh, bih, bhh, wcomb, gbias);
    gemm128_kernel<<<dim3(ATT / 128, MM / 128), 256>>>(features, U_w, U_b, uhs,
                                                       MM, ATT, ENC);

    // ---- sequential decode ----
    for (int t = 0; t < TT; t++) {
        // w_ah = h @ W_w + W_b   (split-K x4)
        gemm64_kernel<<<dim3(ATT / 64, BB / 64, 4), 256>>>(h, W_w, nullptr, part,
                                                           BB, ATT, DEC, ATT, 4, 1);
        reduce_split_kernel<<<(BB * ATT + 255) / 256, 256>>>(part, W_b, wah,
                                                             BB * ATT, ATT, 4);
        // scores = tanh(u_hs + w_ah) . A_w + A_b
        scores_kernel<<<(BB * NN * 32) / 256, 256>>>(uhs, wah, A_w, A_b, scores);
        // alpha = softmax(scores); also write output alphas
        softmax_kernel<<<BB, 256>>>(scores, alpha, alphas, t);
        // context = alpha @ features
        context_kernel<<<dim3(ENC / 256, BB), 256>>>(features, alpha, ctx);
        // x = [emb_t | context | h]
        xcat_kernel<<<dim3(XK / 256, BB), 256>>>(emb, captions, ctx, h, x, t);
        // gates = x @ Wcomb + (bih+bhh)  (split-K x4)
        gemm64_kernel<<<dim3(G4 / 64, BB / 64, 4), 256>>>(x, wcomb, nullptr, part,
                                                          BB, G4, XK, G4, 4, 1);
        reduce_split_kernel<<<(BB * G4 + 255) / 256, 256>>>(part, gbias, gates,
                                                            BB * G4, G4, 4);
        // LSTM pointwise update
        lstm_kernel<<<(BB * DEC + 255) / 256, 256>>>(gates, h, c);
        // preds[:, t, :] = h @ fcn_w + fcn_b
        gemm64_kernel<<<dim3((VV + 63) / 64, BB / 64, 1), 256>>>(h, fcn_w, fcn_b,
                                                                 preds + (size_t)t * VV,
                                                                 BB, VV, DEC, TT * VV, 1, 0);
    }
}